// round 2
// baseline (speedup 1.0000x reference)
#include <cuda_runtime.h>
#include <cstddef>

// ---------------------------------------------------------------------------
// Collapsed model (only pyramid level L-1 survives the reference):
//   g[b,f]      = (1/256) * sum over 16x16 patch grid of x   (f = c*256+pi*16+pj)
//   root[b,d]   = sum_f W_emb[d,f]*g[b,f] + b_emb[d] + pos4[d]
//   out[b,o]    = sum_d W_cls[o,d]*root[b,d] + b_cls[o]
//
// k1 fuses pooling + the W_emb GEMM: each block owns a contiguous 64-wide
// f-slice (block = (q,c,b)), computes its g slice, stages the 128x64 W_emb
// tile in shared, and writes a deterministic partial root contribution.
// k3 sums the 12 partials, adds biases, and does the classifier GEMM.
// ---------------------------------------------------------------------------

__device__ float root_part[12 * 64 * 128];   // [p=(q*3+c)][b][d], 393 KB

// ---------------------------------------------------------------------------
// Kernel 1: pooling + partial embedding.
// grid (4 row-phases, 3 channels, 64 batch), 256 threads.
// Thread (rbase=t>>6, c4=t&63) owns pi = 4q+rbase, float4-column c4; sums 16
// rows with 4 independent accumulators for MLP depth.  Warp loads are 512B
// contiguous.  Then W_emb[0..127][fbase..fbase+63] is staged in shared
// (stride 65 -> conflict-free) and the block emits root_part[q*3+c][b][0..127].
// ---------------------------------------------------------------------------
__global__ __launch_bounds__(256, 5) void k1_pool_emb(
    const float* __restrict__ x, const float* __restrict__ W_emb) {
    const int q = blockIdx.x;    // 0..3 row phase
    const int c = blockIdx.y;    // 0..2 channel
    const int b = blockIdx.z;    // 0..63 batch
    const int t = threadIdx.x;
    const int rbase = t >> 6;    // 0..3
    const int c4 = t & 63;       // float4 column
    const int pi = q * 4 + rbase;

    const float4* plane =
        reinterpret_cast<const float4*>(x + ((size_t)(b * 3 + c) << 16));

    float4 a0 = make_float4(0.f, 0.f, 0.f, 0.f);
    float4 a1 = a0, a2 = a0, a3 = a0;
#pragma unroll
    for (int mm = 0; mm < 4; mm++) {
        float4 v0 = plane[(pi + 16 * (4 * mm + 0)) * 64 + c4];
        float4 v1 = plane[(pi + 16 * (4 * mm + 1)) * 64 + c4];
        float4 v2 = plane[(pi + 16 * (4 * mm + 2)) * 64 + c4];
        float4 v3 = plane[(pi + 16 * (4 * mm + 3)) * 64 + c4];
        a0.x += v0.x; a0.y += v0.y; a0.z += v0.z; a0.w += v0.w;
        a1.x += v1.x; a1.y += v1.y; a1.z += v1.z; a1.w += v1.w;
        a2.x += v2.x; a2.y += v2.y; a2.z += v2.z; a2.w += v2.w;
        a3.x += v3.x; a3.y += v3.y; a3.z += v3.z; a3.w += v3.w;
    }
    float4 acc = make_float4(a0.x + a1.x + a2.x + a3.x,
                             a0.y + a1.y + a2.y + a3.y,
                             a0.z + a1.z + a2.z + a3.z,
                             a0.w + a1.w + a2.w + a3.w);

    __shared__ float4 s[4][64];          // column partials
    __shared__ float wsh[128 * 65];      // W_emb tile, padded stride
    __shared__ float g_sh[64];           // this block's g slice
    __shared__ float ps[256];            // half-combine

    s[rbase][c4] = acc;

    // Stage W_emb tile: rows d=0..127, cols fbase..fbase+63 (contiguous f).
    const int fbase = c * 256 + q * 64;
#pragma unroll
    for (int i = 0; i < 8; i++) {
        int idx4 = t + 256 * i;          // 0..2047 float4 slots
        int d = idx4 >> 4;               // 0..127
        int fq = idx4 & 15;              // float4 within row
        float4 w = *reinterpret_cast<const float4*>(W_emb + d * 768 + fbase + fq * 4);
        float* dst = &wsh[d * 65 + fq * 4];
        dst[0] = w.x; dst[1] = w.y; dst[2] = w.z; dst[3] = w.w;
    }
    __syncthreads();

    if (t < 16) {
        const int rb = t >> 2;
        const int qq = t & 3;
        float4 sum = make_float4(0.f, 0.f, 0.f, 0.f);
#pragma unroll
        for (int j = 0; j < 16; j++) {
            float4 v = s[rb][qq + 4 * j];
            sum.x += v.x; sum.y += v.y; sum.z += v.z; sum.w += v.w;
        }
        const float sc = 1.0f / 256.0f;
        const int fo = rb * 16 + qq * 4;
        g_sh[fo + 0] = sum.x * sc;
        g_sh[fo + 1] = sum.y * sc;
        g_sh[fo + 2] = sum.z * sc;
        g_sh[fo + 3] = sum.w * sc;
    }
    __syncthreads();

    // Partial root: thread (d = t&127, half = t>>7) does 32 FMAs.
    {
        const int d = t & 127;
        const int half = t >> 7;
        const float* wrow = &wsh[d * 65 + half * 32];
        const float* gp = &g_sh[half * 32];
        float acc2 = 0.f;
#pragma unroll
        for (int j = 0; j < 32; j++) acc2 += wrow[j] * gp[j];
        ps[t] = acc2;
    }
    __syncthreads();
    if (t < 128) {
        root_part[((q * 3 + c) * 64 + b) * 128 + t] = ps[t] + ps[t + 128];
    }
}

// ---------------------------------------------------------------------------
// Kernel 3: out = (sum_p root_part + b_emb + pos4) @ W_cls^T + b_cls.
// grid (32 o-tiles, 8 b-tiles), 128 threads.  Warp does 8 o's; root for 8
// batches rebuilt in registers (deterministic partial sum), k=128 over lanes.
// ---------------------------------------------------------------------------
__global__ __launch_bounds__(128) void k3_logits(
    const float* __restrict__ W_cls, const float* __restrict__ b_cls,
    const float* __restrict__ b_emb, const float* __restrict__ pos4,
    float* __restrict__ out) {
    const int ot = blockIdx.x;   // 0..31
    const int bt = blockIdx.y;   // 0..7
    const int t = threadIdx.x;
    const int wid = t >> 5;
    const int lane = t & 31;

    float rreg[8][4];
#pragma unroll
    for (int i = 0; i < 4; i++) {
        const int d = lane + 32 * i;
        const float bias = b_emb[d] + pos4[d];
#pragma unroll
        for (int j = 0; j < 8; j++) rreg[j][i] = bias;
    }
#pragma unroll 2
    for (int p = 0; p < 12; p++) {
        const float* base = root_part + (p * 64 + bt * 8) * 128;
#pragma unroll
        for (int i = 0; i < 4; i++) {
            const int d = lane + 32 * i;
#pragma unroll
            for (int j = 0; j < 8; j++) rreg[j][i] += base[j * 128 + d];
        }
    }

#pragma unroll
    for (int oo = 0; oo < 8; oo++) {
        const int o = ot * 32 + wid * 8 + oo;
        if (o < 1000) {
            const float* wp = W_cls + o * 128 + lane;
            float acc[8];
#pragma unroll
            for (int j = 0; j < 8; j++) acc[j] = 0.f;
#pragma unroll
            for (int i = 0; i < 4; i++) {
                float w = wp[i * 32];
#pragma unroll
                for (int j = 0; j < 8; j++) acc[j] += w * rreg[j][i];
            }
#pragma unroll
            for (int off = 16; off >= 1; off >>= 1) {
#pragma unroll
                for (int j = 0; j < 8; j++)
                    acc[j] += __shfl_xor_sync(0xffffffffu, acc[j], off);
            }
            if (lane == 0) {
                const float bc = b_cls[o];
#pragma unroll
                for (int j = 0; j < 8; j++)
                    out[(bt * 8 + j) * 1000 + o] = acc[j] + bc;
            }
        }
    }
}

// ---------------------------------------------------------------------------
// Inputs (metadata order): 0:x 1:W_emb 2:b_emb 3:pos0 4:pos1 5:pos2 6:pos3
//                          7:pos4 8:W_cls 9:b_cls.  Output: (64,1000) f32.
// ---------------------------------------------------------------------------
extern "C" void kernel_launch(void* const* d_in, const int* in_sizes, int n_in,
                              void* d_out, int out_size) {
    const float* x     = (const float*)d_in[0];
    const float* W_emb = (const float*)d_in[1];
    const float* b_emb = (const float*)d_in[2];
    const float* pos4  = (const float*)d_in[7];
    const float* W_cls = (const float*)d_in[8];
    const float* b_cls = (const float*)d_in[9];
    float* out = (float*)d_out;

    k1_pool_emb<<<dim3(4, 3, 64), 256>>>(x, W_emb);
    k3_logits<<<dim3(32, 8), 128>>>(W_cls, b_cls, b_emb, pos4, out);
}

// round 3
// speedup vs baseline: 1.1810x; 1.1810x over previous
#include <cuda_runtime.h>
#include <cstddef>

// ---------------------------------------------------------------------------
// Collapsed model (only pyramid level L-1 survives the reference):
//   g[b,f]    = (1/256) * sum over 16x16 patch grid of x   (f = c*256+pi*16+pj)
//   root[b,d] = sum_f W_emb[d,f]*g[b,f] + b_emb[d] + pos4[d]
//   out[b,o]  = sum_d W_cls[o,d]*root[b,d] + b_cls[o]
// Three kernels: pooling (HBM-bound), embed GEMM (tiny), classifier GEMM (tiny).
// ---------------------------------------------------------------------------

__device__ float g_scratch[64 * 768];      // 196 KB
__device__ float root_scratch[64 * 128];   // 32 KB

// ---------------------------------------------------------------------------
// Kernel 1: strided pooling of x.  grid (4 row-phases, 3 channels, 64 batch),
// 256 threads.  Thread (rbase=t>>6, c4=t&63) owns pi = 4q+rbase, float4-col
// c4; sums 16 rows.  Loads are front-batched 8-deep (two waves) for MLP.
// Block exclusively owns 4 pi rows -> exact final writes of g, no atomics.
// ---------------------------------------------------------------------------
__global__ __launch_bounds__(256, 4) void k1_pool(const float* __restrict__ x) {
    const int q = blockIdx.x;    // 0..3 row phase
    const int c = blockIdx.y;    // 0..2 channel
    const int b = blockIdx.z;    // 0..63 batch
    const int t = threadIdx.x;
    const int rbase = t >> 6;    // 0..3
    const int c4 = t & 63;       // float4 column 0..63
    const int pi = q * 4 + rbase;

    const float4* plane =
        reinterpret_cast<const float4*>(x + ((size_t)(b * 3 + c) << 16));

    float4 acc0 = make_float4(0.f, 0.f, 0.f, 0.f);
    float4 acc1 = acc0, acc2 = acc0, acc3 = acc0;

#pragma unroll
    for (int h = 0; h < 2; h++) {
        float4 v[8];
#pragma unroll
        for (int i = 0; i < 8; i++)
            v[i] = plane[(pi + 16 * (8 * h + i)) * 64 + c4];
#pragma unroll
        for (int i = 0; i < 8; i++) {
            float4* a = (i & 3) == 0 ? &acc0 : (i & 3) == 1 ? &acc1
                       : (i & 3) == 2 ? &acc2 : &acc3;
            a->x += v[i].x; a->y += v[i].y; a->z += v[i].z; a->w += v[i].w;
        }
    }
    float4 acc = make_float4(acc0.x + acc1.x + acc2.x + acc3.x,
                             acc0.y + acc1.y + acc2.y + acc3.y,
                             acc0.z + acc1.z + acc2.z + acc3.z,
                             acc0.w + acc1.w + acc2.w + acc3.w);

    __shared__ float4 s[4][64];
    s[rbase][c4] = acc;
    __syncthreads();

    if (t < 16) {
        const int rb = t >> 2;   // 0..3
        const int qq = t & 3;    // pj quad 0..3
        float4 sum = make_float4(0.f, 0.f, 0.f, 0.f);
#pragma unroll
        for (int j = 0; j < 16; j++) {
            float4 v = s[rb][qq + 4 * j];
            sum.x += v.x; sum.y += v.y; sum.z += v.z; sum.w += v.w;
        }
        const float sc = 1.0f / 256.0f;
        const int pi2 = q * 4 + rb;
        float4* gout = reinterpret_cast<float4*>(
            g_scratch + b * 768 + c * 256 + pi2 * 16 + qq * 4);
        *gout = make_float4(sum.x * sc, sum.y * sc, sum.z * sc, sum.w * sc);
    }
}

// ---------------------------------------------------------------------------
// Kernel 2: root = g @ W_emb^T + (b_emb + pos4).
// grid (8 d-tiles, 32 b-tiles), 128 threads (4 warps).  Each warp does 4 d's,
// k=768 split over lanes (24 regs of g per batch, 2 batches), shfl-reduce.
// ---------------------------------------------------------------------------
__global__ __launch_bounds__(128) void k2_root(const float* __restrict__ W_emb,
                                               const float* __restrict__ b_emb,
                                               const float* __restrict__ pos4) {
    const int dt = blockIdx.x;   // 0..7
    const int bt = blockIdx.y;   // 0..31 (2 batches each)
    const int t = threadIdx.x;
    const int wid = t >> 5;
    const int lane = t & 31;

    float greg[2][24];
#pragma unroll
    for (int j = 0; j < 2; j++) {
        const float* gp = g_scratch + (bt * 2 + j) * 768 + lane;
#pragma unroll
        for (int i = 0; i < 24; i++) greg[j][i] = gp[i * 32];
    }

#pragma unroll
    for (int dd = 0; dd < 4; dd++) {
        const int d = dt * 16 + wid * 4 + dd;
        const float* wp = W_emb + d * 768 + lane;
        float a0 = 0.f, a1 = 0.f;
#pragma unroll
        for (int i = 0; i < 24; i++) {
            float w = wp[i * 32];
            a0 += w * greg[0][i];
            a1 += w * greg[1][i];
        }
#pragma unroll
        for (int off = 16; off >= 1; off >>= 1) {
            a0 += __shfl_xor_sync(0xffffffffu, a0, off);
            a1 += __shfl_xor_sync(0xffffffffu, a1, off);
        }
        if (lane == 0) {
            const float bias = b_emb[d] + pos4[d];
            root_scratch[(bt * 2 + 0) * 128 + d] = a0 + bias;
            root_scratch[(bt * 2 + 1) * 128 + d] = a1 + bias;
        }
    }
}

// ---------------------------------------------------------------------------
// Kernel 3: out = root @ W_cls^T + b_cls.
// grid (32 o-tiles, 8 b-tiles), 128 threads.  Warp does 8 o's; root for 8
// batches held in registers (32 regs), k=128 over lanes, shfl-reduce.
// ---------------------------------------------------------------------------
__global__ __launch_bounds__(128) void k3_logits(const float* __restrict__ W_cls,
                                                 const float* __restrict__ b_cls,
                                                 float* __restrict__ out) {
    const int ot = blockIdx.x;   // 0..31
    const int bt = blockIdx.y;   // 0..7
    const int t = threadIdx.x;
    const int wid = t >> 5;
    const int lane = t & 31;

    float rreg[8][4];
#pragma unroll
    for (int j = 0; j < 8; j++) {
        const float* rp = root_scratch + (bt * 8 + j) * 128 + lane;
#pragma unroll
        for (int i = 0; i < 4; i++) rreg[j][i] = rp[i * 32];
    }

#pragma unroll
    for (int oo = 0; oo < 8; oo++) {
        const int o = ot * 32 + wid * 8 + oo;
        if (o < 1000) {
            const float* wp = W_cls + o * 128 + lane;
            float acc[8];
#pragma unroll
            for (int j = 0; j < 8; j++) acc[j] = 0.f;
#pragma unroll
            for (int i = 0; i < 4; i++) {
                float w = wp[i * 32];
#pragma unroll
                for (int j = 0; j < 8; j++) acc[j] += w * rreg[j][i];
            }
#pragma unroll
            for (int off = 16; off >= 1; off >>= 1) {
#pragma unroll
                for (int j = 0; j < 8; j++)
                    acc[j] += __shfl_xor_sync(0xffffffffu, acc[j], off);
            }
            if (lane == 0) {
                const float bc = b_cls[o];
#pragma unroll
                for (int j = 0; j < 8; j++)
                    out[(bt * 8 + j) * 1000 + o] = acc[j] + bc;
            }
        }
    }
}

// ---------------------------------------------------------------------------
// Inputs (metadata order): 0:x 1:W_emb 2:b_emb 3:pos0 4:pos1 5:pos2 6:pos3
//                          7:pos4 8:W_cls 9:b_cls.  Output: (64,1000) f32.
// ---------------------------------------------------------------------------
extern "C" void kernel_launch(void* const* d_in, const int* in_sizes, int n_in,
                              void* d_out, int out_size) {
    const float* x     = (const float*)d_in[0];
    const float* W_emb = (const float*)d_in[1];
    const float* b_emb = (const float*)d_in[2];
    const float* pos4  = (const float*)d_in[7];
    const float* W_cls = (const float*)d_in[8];
    const float* b_cls = (const float*)d_in[9];
    float* out = (float*)d_out;

    k1_pool<<<dim3(4, 3, 64), 256>>>(x);
    k2_root<<<dim3(8, 32), 128>>>(W_emb, b_emb, pos4);
    k3_logits<<<dim3(32, 8), 128>>>(W_cls, b_cls, out);
}

// round 4
// speedup vs baseline: 1.4858x; 1.2581x over previous
#include <cuda_runtime.h>
#include <cstddef>

// ---------------------------------------------------------------------------
// Collapsed model (only pyramid level L-1 survives the reference):
//   g[b,f]    = (1/256) * sum over 16x16 patch grid of x   (f = c*256+pi*16+pj)
//   root[b,d] = sum_f W_emb[d,f]*g[b,f] + b_emb[d] + pos4[d]
//   out[b,o]  = sum_d W_cls[o,d]*root[b,d] + b_cls[o]
// ---------------------------------------------------------------------------

__device__ float g_scratch[64 * 768];      // 196 KB
__device__ float root_scratch[64 * 128];   // 32 KB

// ---------------------------------------------------------------------------
// Kernel 1: strided pooling of x.
// grid (16 pi-rows, 3 channels, 64 batch) = 3072 blocks of 64 threads,
// ~21 co-resident blocks/SM (regs capped to 48) -> one well-balanced wave.
// Thread t loads float4 column t of rows pi+16m (warp = 512B contiguous),
// sums over bh in registers, reduces over bw with 3 butterfly shuffles,
// cross-warp combine through 128B of shared, 4 threads store the final
// 16 floats of g for this (b,c,pi).  No long serial tail.
// ---------------------------------------------------------------------------
__global__ __launch_bounds__(64, 21) void k1_pool(const float* __restrict__ x) {
    const int pi = blockIdx.x;   // 0..15 row within patch
    const int c  = blockIdx.y;   // 0..2 channel
    const int b  = blockIdx.z;   // 0..63 batch
    const int t  = threadIdx.x;  // 0..63 float4 column

    const float4* plane =
        reinterpret_cast<const float4*>(x + ((size_t)(b * 3 + c) << 16));

    float4 a0 = make_float4(0.f, 0.f, 0.f, 0.f);
    float4 a1 = a0, a2 = a0, a3 = a0;
#pragma unroll
    for (int m = 0; m < 16; m += 4) {
        float4 v0 = plane[(pi + 16 * (m + 0)) * 64 + t];
        float4 v1 = plane[(pi + 16 * (m + 1)) * 64 + t];
        float4 v2 = plane[(pi + 16 * (m + 2)) * 64 + t];
        float4 v3 = plane[(pi + 16 * (m + 3)) * 64 + t];
        a0.x += v0.x; a0.y += v0.y; a0.z += v0.z; a0.w += v0.w;
        a1.x += v1.x; a1.y += v1.y; a1.z += v1.z; a1.w += v1.w;
        a2.x += v2.x; a2.y += v2.y; a2.z += v2.z; a2.w += v2.w;
        a3.x += v3.x; a3.y += v3.y; a3.z += v3.z; a3.w += v3.w;
    }
    // acc = sum over bh for cols 4t..4t+3  (bw = t>>2, pj = 4*(t&3)+j)
    float4 acc = make_float4(a0.x + a1.x + a2.x + a3.x,
                             a0.y + a1.y + a2.y + a3.y,
                             a0.z + a1.z + a2.z + a3.z,
                             a0.w + a1.w + a2.w + a3.w);

    // Reduce over bw within the warp: lanes with equal (t&3) differ in t>>2.
#pragma unroll
    for (int off = 4; off <= 16; off <<= 1) {
        acc.x += __shfl_xor_sync(0xffffffffu, acc.x, off);
        acc.y += __shfl_xor_sync(0xffffffffu, acc.y, off);
        acc.z += __shfl_xor_sync(0xffffffffu, acc.z, off);
        acc.w += __shfl_xor_sync(0xffffffffu, acc.w, off);
    }

    __shared__ float4 s2[2][4];
    if ((t & 31) < 4) s2[t >> 5][t & 3] = acc;
    __syncthreads();

    if (t < 4) {
        float4 r0 = s2[0][t];
        float4 r1 = s2[1][t];
        const float sc = 1.0f / 256.0f;
        float4 out = make_float4((r0.x + r1.x) * sc, (r0.y + r1.y) * sc,
                                 (r0.z + r1.z) * sc, (r0.w + r1.w) * sc);
        reinterpret_cast<float4*>(g_scratch + b * 768 + c * 256 + pi * 16)[t] = out;
    }
}

// ---------------------------------------------------------------------------
// Kernel 2 (R1 version): root = g @ W_emb^T + (b_emb + pos4).
// grid (8 d-tiles, 16 b-tiles), 128 threads.  Warp does 4 d's, k=768 over
// lanes (24 g regs per batch, 4 batches), shfl-reduce.
// ---------------------------------------------------------------------------
__global__ __launch_bounds__(128) void k2_root(const float* __restrict__ W_emb,
                                               const float* __restrict__ b_emb,
                                               const float* __restrict__ pos4) {
    const int dt = blockIdx.x;   // 0..7
    const int bt = blockIdx.y;   // 0..15
    const int t = threadIdx.x;
    const int wid = t >> 5;
    const int lane = t & 31;

    float greg[4][24];
#pragma unroll
    for (int j = 0; j < 4; j++) {
        const float* gp = g_scratch + (bt * 4 + j) * 768 + lane;
#pragma unroll
        for (int i = 0; i < 24; i++) greg[j][i] = gp[i * 32];
    }

#pragma unroll
    for (int dd = 0; dd < 4; dd++) {
        const int d = dt * 16 + wid * 4 + dd;
        const float* wp = W_emb + d * 768 + lane;
        float a0 = 0.f, a1 = 0.f, a2 = 0.f, a3 = 0.f;
#pragma unroll
        for (int i = 0; i < 24; i++) {
            float w = wp[i * 32];
            a0 += w * greg[0][i];
            a1 += w * greg[1][i];
            a2 += w * greg[2][i];
            a3 += w * greg[3][i];
        }
#pragma unroll
        for (int off = 16; off >= 1; off >>= 1) {
            a0 += __shfl_xor_sync(0xffffffffu, a0, off);
            a1 += __shfl_xor_sync(0xffffffffu, a1, off);
            a2 += __shfl_xor_sync(0xffffffffu, a2, off);
            a3 += __shfl_xor_sync(0xffffffffu, a3, off);
        }
        if (lane == 0) {
            const float bias = b_emb[d] + pos4[d];
            root_scratch[(bt * 4 + 0) * 128 + d] = a0 + bias;
            root_scratch[(bt * 4 + 1) * 128 + d] = a1 + bias;
            root_scratch[(bt * 4 + 2) * 128 + d] = a2 + bias;
            root_scratch[(bt * 4 + 3) * 128 + d] = a3 + bias;
        }
    }
}

// ---------------------------------------------------------------------------
// Kernel 3 (R1 version): out = root @ W_cls^T + b_cls.
// grid (32 o-tiles, 8 b-tiles), 128 threads.
// ---------------------------------------------------------------------------
__global__ __launch_bounds__(128) void k3_logits(const float* __restrict__ W_cls,
                                                 const float* __restrict__ b_cls,
                                                 float* __restrict__ out) {
    const int ot = blockIdx.x;   // 0..31
    const int bt = blockIdx.y;   // 0..7
    const int t = threadIdx.x;
    const int wid = t >> 5;
    const int lane = t & 31;

    float rreg[8][4];
#pragma unroll
    for (int j = 0; j < 8; j++) {
        const float* rp = root_scratch + (bt * 8 + j) * 128 + lane;
#pragma unroll
        for (int i = 0; i < 4; i++) rreg[j][i] = rp[i * 32];
    }

#pragma unroll
    for (int oo = 0; oo < 8; oo++) {
        const int o = ot * 32 + wid * 8 + oo;
        if (o < 1000) {
            const float* wp = W_cls + o * 128 + lane;
            float acc[8];
#pragma unroll
            for (int j = 0; j < 8; j++) acc[j] = 0.f;
#pragma unroll
            for (int i = 0; i < 4; i++) {
                float w = wp[i * 32];
#pragma unroll
                for (int j = 0; j < 8; j++) acc[j] += w * rreg[j][i];
            }
#pragma unroll
            for (int off = 16; off >= 1; off >>= 1) {
#pragma unroll
                for (int j = 0; j < 8; j++)
                    acc[j] += __shfl_xor_sync(0xffffffffu, acc[j], off);
            }
            if (lane == 0) {
                const float bc = b_cls[o];
#pragma unroll
                for (int j = 0; j < 8; j++)
                    out[(bt * 8 + j) * 1000 + o] = acc[j] + bc;
            }
        }
    }
}

// ---------------------------------------------------------------------------
// Inputs (metadata order): 0:x 1:W_emb 2:b_emb 3:pos0 4:pos1 5:pos2 6:pos3
//                          7:pos4 8:W_cls 9:b_cls.  Output: (64,1000) f32.
// ---------------------------------------------------------------------------
extern "C" void kernel_launch(void* const* d_in, const int* in_sizes, int n_in,
                              void* d_out, int out_size) {
    const float* x     = (const float*)d_in[0];
    const float* W_emb = (const float*)d_in[1];
    const float* b_emb = (const float*)d_in[2];
    const float* pos4  = (const float*)d_in[7];
    const float* W_cls = (const float*)d_in[8];
    const float* b_cls = (const float*)d_in[9];
    float* out = (float*)d_out;

    k1_pool<<<dim3(16, 3, 64), 64>>>(x);
    k2_root<<<dim3(8, 16), 128>>>(W_emb, b_emb, pos4);
    k3_logits<<<dim3(32, 8), 128>>>(W_cls, b_cls, out);
}